// round 10
// baseline (speedup 1.0000x reference)
#include <cuda_runtime.h>
#include <math.h>

#define BSZ 4
#define CC  4
#define NN  2048
#define DD  16
#define KK  32
#define MM  64
#define FULLM 0xffffffffu
typedef unsigned long long ull;
#define INF32 0xffffffffu
#define INF64 0xFFFFFFFFFFFFFFFFull

// scratch (allocation-free rule: device globals)
__device__ int   g_nbr  [BSZ*CC*NN*KK];
__device__ float g_theta[BSZ*CC*NN*KK];
__device__ float g_gate [BSZ*CC*NN*KK];
__device__ float g_gsum [BSZ*CC*NN];
__device__ float g_awT  [128*MM];

__device__ __forceinline__ ull warpmin64(ull p) {
    #pragma unroll
    for (int o = 16; o; o >>= 1) {
        ull q = __shfl_xor_sync(FULLM, p, o);
        if (q < p) p = q;
    }
    return p;
}

// bitonic compare-exchange steps (warp-wide, 2 elements/lane)
__device__ __forceinline__ unsigned cex32(unsigned v, int j, bool up, int lane) {
    unsigned o = __shfl_xor_sync(FULLM, v, j);
    bool low = ((lane & j) == 0);
    unsigned mn = min(v, o), mx = max(v, o);
    return (low == up) ? mn : mx;
}
__device__ __forceinline__ ull cex64(ull v, int j, bool up, int lane) {
    ull o = __shfl_xor_sync(FULLM, v, j);
    bool low = ((lane & j) == 0);
    ull mn = (v < o) ? v : o;
    ull mx = (v < o) ? o : v;
    return (low == up) ? mn : mx;
}

__device__ __forceinline__ void emit_row(
    int slice, int b, int i, unsigned nbd, int nbj,
    float Spos, const float* node_mask, const float4* spos, int lane)
{
    const float4 pi  = spos[i];
    const float mk   = node_mask[b*NN + i];
    const float dist = __uint_as_float(nbd);
    const int   nb   = nbj;

    const int nb0 = __shfl_sync(FULLM, nbj, 0);
    float4 pn0 = spos[nb0];
    float d0x = pn0.x - pi.x, d0y = pn0.y - pi.y, d0z = pn0.z - pi.z;
    float n0  = sqrtf(d0x*d0x + d0y*d0y + d0z*d0z);
    float inv0 = 1.f / fmaxf(n0, 1e-12f);
    d0x *= inv0; d0y *= inv0; d0z *= inv0;

    float cosv = 1.f;
    if (lane > 0) {
        float4 pn = spos[nb];
        float dx = pn.x - pi.x, dy = pn.y - pi.y, dz = pn.z - pi.z;
        float nrm = sqrtf(dx*dx + dy*dy + dz*dz);
        float inv = 1.f / fmaxf(nrm, 1e-12f);
        cosv = (dx*d0x + dy*d0y + dz*d0z) * inv;
    }
    const float gb   = fmaxf(dist * Spos, 0.f) * mk;
    const float gate = 1.f / (1.f + __expf(-gb));

    float G = gate;
    #pragma unroll
    for (int o = 16; o; o >>= 1) G += __shfl_xor_sync(FULLM, G, o);

    const size_t base = ((size_t)slice * NN + i) * KK;
    g_nbr  [base + lane] = nb;
    g_theta[base + lane] = cosv * mk;
    g_gate [base + lane] = gate;
    if (lane == 0) g_gsum[(size_t)slice*NN + i] = G;
}

// ---------------------------------------------------------------------------
// Kernel 1 v9 (unchanged): warp-per-row threshold select.
// ---------------------------------------------------------------------------
__global__ __launch_bounds__(512, 3) void knn_kernel(
    const float* __restrict__ pos, const float* __restrict__ node_mask,
    const float* __restrict__ rw1, const float* __restrict__ rw2,
    const float* __restrict__ aw)
{
    __shared__ float4 spos[NN];            // 32KB
    __shared__ ull    srow[16][64];        // 8KB survivor buffers
    __shared__ int    scnt[16];
    __shared__ float  sSpos;

    const int tid  = threadIdx.x;
    const int warp = tid >> 5;
    const int lane = tid & 31;
    const int slice = blockIdx.y;          // b*C + c
    const int b     = slice >> 2;
    const float* p  = pos + (size_t)slice * NN * 3;

    for (int j = tid; j < NN; j += 512) {
        float x = p[3*j], y = p[3*j+1], z = p[3*j+2];
        float q = fmaf(z, z, fmaf(y, y, x*x));
        spos[j] = make_float4(x, y, z, q);
    }

    // fold the aw transpose into one knn block (fuse runs after knn)
    if (blockIdx.x == 0 && slice == 0) {
        for (int idx = tid; idx < 128*MM; idx += 512) {
            int f = idx >> 6, m = idx & 63;
            g_awT[idx] = aw[m*128 + f];
        }
    }

    // gate MLP collapses: relu(sum_m relu(d*w1)*w2) = relu(d*Spos) for d>=0
    if (tid < 32) {
        float a1 = rw1[tid],    w1v = rw2[tid];
        float a2 = rw1[tid+32], w2v = rw2[tid+32];
        float sp = fmaf(fmaxf(a1, 0.f), w1v, fmaxf(a2, 0.f) * w2v);
        #pragma unroll
        for (int o = 16; o; o >>= 1) sp += __shfl_xor_sync(FULLM, sp, o);
        if (tid == 0) sSpos = sp;
    }
    __syncthreads();

    const int i = blockIdx.x * 16 + warp;
    const float4 pi = spos[i];

    // pass 1: per-lane two smallest d values (u32; d>=0 so bit order = value)
    unsigned h0 = INF32, h1 = INF32;
    #pragma unroll 4
    for (int t = 0; t < 64; t++) {
        float4 pj = spos[t*32 + lane];
        float dot = fmaf(pi.z, pj.z, fmaf(pi.y, pj.y, pi.x * pj.x));
        float d   = fmaxf(fmaf(-2.f, dot, pj.w) + pi.w, 0.f);
        unsigned u = __float_as_uint(d);
        bool c0 = u < h0, c1 = u < h1;
        h1 = c0 ? h0 : (c1 ? u : h1);
        h0 = c0 ? u : h0;
    }

    // bitonic sort the 64 head d's ascending; T = rank 32 (33rd smallest).
    {
        unsigned v0 = h0, v1 = h1;
        #pragma unroll
        for (int k = 2; k <= 32; k <<= 1) {
            #pragma unroll
            for (int j = k >> 1; j > 0; j >>= 1) {
                bool up0 = ((lane & k) == 0);
                bool up1 = (((lane + 32) & k) == 0);
                v0 = cex32(v0, j, up0, lane);
                v1 = cex32(v1, j, up1, lane);
            }
        }
        { unsigned lo = min(v0, v1), hi = max(v0, v1); v0 = lo; v1 = hi; }
        #pragma unroll
        for (int j = 16; j > 0; j >>= 1) {
            v0 = cex32(v0, j, true, lane);
            v1 = cex32(v1, j, true, lane);
        }
        h0 = __shfl_sync(FULLM, v1, 0);    // T (reuse h0)
    }
    const unsigned T = h0;

    // init survivor buffer
    if (lane == 0) scnt[warp] = 0;
    srow[warp][lane]      = INF64;
    srow[warp][lane + 32] = INF64;
    __syncwarp();

    // pass 2: compact survivors (d <= T) with (d,j) keys
    #pragma unroll 4
    for (int t = 0; t < 64; t++) {
        const int j = t*32 + lane;
        float4 pj = spos[j];
        float dot = fmaf(pi.z, pj.z, fmaf(pi.y, pj.y, pi.x * pj.x));
        float d   = fmaxf(fmaf(-2.f, dot, pj.w) + pi.w, 0.f);
        unsigned u = __float_as_uint(d);
        if (u <= T) {
            int idx = atomicAdd(&scnt[warp], 1);
            if (idx < 64) srow[warp][idx] = ((ull)u << 32) | (unsigned)j;
        }
    }
    __syncwarp();
    const int S = scnt[warp];              // guaranteed >= 33

    unsigned nbd = 0; int nbj = 0;
    if (S <= 64) {
        // bitonic sort the 64 padded (d,j) keys; ranks 1..32 = neighbors
        ull V0 = srow[warp][lane], V1 = srow[warp][lane + 32];
        #pragma unroll
        for (int k = 2; k <= 32; k <<= 1) {
            #pragma unroll
            for (int j = k >> 1; j > 0; j >>= 1) {
                bool up0 = ((lane & k) == 0);
                bool up1 = (((lane + 32) & k) == 0);
                V0 = cex64(V0, j, up0, lane);
                V1 = cex64(V1, j, up1, lane);
            }
        }
        { ull lo = (V0 < V1) ? V0 : V1; ull hi = (V0 < V1) ? V1 : V0;
          V0 = lo; V1 = hi; }
        #pragma unroll
        for (int j = 16; j > 0; j >>= 1) {
            V0 = cex64(V0, j, true, lane);
            V1 = cex64(V1, j, true, lane);
        }
        // lane k takes rank k+1 (rank 0 = self)
        ull a  = __shfl_sync(FULLM, V0, (lane + 1) & 31);
        ull bq = __shfl_sync(FULLM, V1, 0);
        ull kk = (lane == 31) ? bq : a;
        nbd = (unsigned)(kk >> 32); nbj = (int)(unsigned)kk;
    } else {
        // exact slow fallback (degenerate data only): 33 min-above-last rounds
        ull last = 0;
        #pragma unroll 1
        for (int e = 0; e <= 32; e++) {
            ull best = INF64;
            for (int t = 0; t < 64; t++) {
                const int j = t*32 + lane;
                float4 pj = spos[j];
                float dot = fmaf(pi.z, pj.z, fmaf(pi.y, pj.y, pi.x * pj.x));
                float d   = fmaxf(fmaf(-2.f, dot, pj.w) + pi.w, 0.f);
                ull key = ((ull)__float_as_uint(d) << 32) | (unsigned)j;
                if ((e == 0 || key > last) && key < best) best = key;
            }
            ull wm = warpmin64(best);
            if (lane == e - 1) { nbd = (unsigned)(wm >> 32); nbj = (int)(unsigned)wm; }
            last = wm;
        }
    }

    emit_row(slice, b, i, nbd, nbj, sSpos, node_mask, spos, lane);
}

// ---------------------------------------------------------------------------
// Kernel 2 v10: 32 nodes/block (grid 256). Phase A prefetches all edge
// indices before feature gathers (max MLP); phase B runs two interleaved
// f-streams (2x independent chains & loads).
// ---------------------------------------------------------------------------
__global__ __launch_bounds__(256) void fuse_kernel(
    const float* __restrict__ node_fea, const float* __restrict__ node_mask,
    const float* __restrict__ sw, float* __restrict__ out)
{
    __shared__ float su [128*34];          // [f][n pitch34]
    __shared__ float sth[128*34];

    const int tid = threadIdx.x;
    const int b   = blockIdx.x >> 6;       // 64 blocks per batch
    const int n0  = (blockIdx.x & 63) * 32;

    // stage theta -> [f = k*4+c][n]
    for (int idx = tid; idx < 4096; idx += 256) {
        int c = idx >> 10, r = idx & 1023, n = r >> 5, k = r & 31;
        sth[(k*4 + c)*34 + n] =
            g_theta[(((size_t)(b*CC + c))*NN + n0 + n)*KK + k];
    }

    // phase A: thread = (c, nn, half); prefetch indices, then batched gathers
    {
        const int c = tid >> 6, r = tid & 63, nn = r >> 1, half = r & 1;
        const float* nf = node_fea + (size_t)(b*CC + c) * NN * DD;
        const float mk = node_mask[b*NN + n0 + nn];
        const float G  = g_gsum[(size_t)(b*CC + c)*NN + n0 + nn];
        const size_t eb = ((size_t)(b*CC + c)*NN + n0 + nn) * KK;

        // prefetch all 32 (gate, nbr): 16 independent 16B loads
        float gs[KK]; int ns[KK];
        #pragma unroll
        for (int k4 = 0; k4 < 8; k4++) {
            float4 g4 = __ldg((const float4*)(g_gate + eb) + k4);
            int4   n4 = __ldg((const int4*)  (g_nbr  + eb) + k4);
            gs[k4*4+0] = g4.x; gs[k4*4+1] = g4.y;
            gs[k4*4+2] = g4.z; gs[k4*4+3] = g4.w;
            ns[k4*4+0] = n4.x; ns[k4*4+1] = n4.y;
            ns[k4*4+2] = n4.z; ns[k4*4+3] = n4.w;
        }

        // all addresses known: 64 independent feature loads
        float4 a0 = {0,0,0,0}, a1 = {0,0,0,0};
        #pragma unroll 8
        for (int k = 0; k < KK; k++) {
            const float4* vp = (const float4*)(nf + (size_t)ns[k]*DD) + half*2;
            float4 v0 = __ldg(vp), v1 = __ldg(vp + 1);
            float g = gs[k];
            a0.x = fmaf(g, v0.x, a0.x); a0.y = fmaf(g, v0.y, a0.y);
            a0.z = fmaf(g, v0.z, a0.z); a0.w = fmaf(g, v0.w, a0.w);
            a1.x = fmaf(g, v1.x, a1.x); a1.y = fmaf(g, v1.y, a1.y);
            a1.z = fmaf(g, v1.z, a1.z); a1.w = fmaf(g, v1.w, a1.w);
        }
        const int fn = c*32 + 16 + half*8;     // neighbor block (masked)
        su[(fn+0)*34+nn] = a0.x*mk;  su[(fn+1)*34+nn] = a0.y*mk;
        su[(fn+2)*34+nn] = a0.z*mk;  su[(fn+3)*34+nn] = a0.w*mk;
        su[(fn+4)*34+nn] = a1.x*mk;  su[(fn+5)*34+nn] = a1.y*mk;
        su[(fn+6)*34+nn] = a1.z*mk;  su[(fn+7)*34+nn] = a1.w*mk;

        const float Gm = G * mk;               // self block
        const float4* fp = (const float4*)(nf + (size_t)(n0+nn)*DD) + half*2;
        float4 f0 = __ldg(fp), f1 = __ldg(fp + 1);
        const int fs = c*32 + half*8;
        su[(fs+0)*34+nn] = Gm*f0.x;  su[(fs+1)*34+nn] = Gm*f0.y;
        su[(fs+2)*34+nn] = Gm*f0.z;  su[(fs+3)*34+nn] = Gm*f0.w;
        su[(fs+4)*34+nn] = Gm*f1.x;  su[(fs+5)*34+nn] = Gm*f1.y;
        su[(fs+6)*34+nn] = Gm*f1.z;  su[(fs+7)*34+nn] = Gm*f1.w;
    }
    __syncthreads();

    // phase B: tile 4m x 2n, TWO interleaved f-streams (f, f+64)
    {
        const int mg = (tid & 15) * 4;
        const int ng = tid >> 4;               // n = ng*2 + {0,1}
        float acc[4][2], bcc[4][2];
        #pragma unroll
        for (int a = 0; a < 4; a++) {
            acc[a][0] = 0.f; acc[a][1] = 0.f;
            bcc[a][0] = 0.f; bcc[a][1] = 0.f;
        }

        #pragma unroll 4
        for (int f = 0; f < 64; f++) {
            float4 w1a = __ldg((const float4*)(sw    + f*64 + mg));
            float4 w2a = __ldg((const float4*)(g_awT + f*64 + mg));
            float4 w1b = __ldg((const float4*)(sw    + (f+64)*64 + mg));
            float4 w2b = __ldg((const float4*)(g_awT + (f+64)*64 + mg));
            float2 ua = *(const float2*)&su [f*34 + ng*2];
            float2 ta = *(const float2*)&sth[f*34 + ng*2];
            float2 ub = *(const float2*)&su [(f+64)*34 + ng*2];
            float2 tb = *(const float2*)&sth[(f+64)*34 + ng*2];
            const float wa1[4] = {w1a.x, w1a.y, w1a.z, w1a.w};
            const float wa2[4] = {w2a.x, w2a.y, w2a.z, w2a.w};
            const float wb1[4] = {w1b.x, w1b.y, w1b.z, w1b.w};
            const float wb2[4] = {w2b.x, w2b.y, w2b.z, w2b.w};
            #pragma unroll
            for (int a = 0; a < 4; a++) {
                acc[a][0] = fmaf(wa1[a], ua.x, fmaf(wa2[a], ta.x, acc[a][0]));
                acc[a][1] = fmaf(wa1[a], ua.y, fmaf(wa2[a], ta.y, acc[a][1]));
                bcc[a][0] = fmaf(wb1[a], ub.x, fmaf(wb2[a], tb.x, bcc[a][0]));
                bcc[a][1] = fmaf(wb1[a], ub.y, fmaf(wb2[a], tb.y, bcc[a][1]));
            }
        }

        const float mk0 = node_mask[b*NN + n0 + ng*2];
        const float mk1 = node_mask[b*NN + n0 + ng*2 + 1];
        #pragma unroll
        for (int a = 0; a < 4; a++) {
            float v0 = acc[a][0] + bcc[a][0];
            float v1 = acc[a][1] + bcc[a][1];
            v0 = (v0 >= 0.f) ? v0 : 0.01f*v0;
            v1 = (v1 >= 0.f) ? v1 : 0.01f*v1;
            float2 o2 = make_float2(v0*mk0, v1*mk1);
            *(float2*)&out[((size_t)b*MM + mg + a)*NN + n0 + ng*2] = o2;
        }
    }
}

// ---------------------------------------------------------------------------
extern "C" void kernel_launch(void* const* d_in, const int* in_sizes, int n_in,
                              void* d_out, int out_size)
{
    const float* pos       = (const float*)d_in[0];
    const float* node_fea  = (const float*)d_in[1];
    const float* node_mask = (const float*)d_in[2];
    const float* aw        = (const float*)d_in[3];
    const float* sw        = (const float*)d_in[4];
    const float* rw1       = (const float*)d_in[5];
    const float* rw2       = (const float*)d_in[6];
    float* out = (float*)d_out;

    knn_kernel<<<dim3(NN/16, BSZ*CC), 512>>>(pos, node_mask, rw1, rw2, aw);
    fuse_kernel<<<BSZ*(NN/32), 256>>>(node_fea, node_mask, sw, out);
}

// round 11
// speedup vs baseline: 1.2122x; 1.2122x over previous
#include <cuda_runtime.h>
#include <math.h>

#define BSZ 4
#define CC  4
#define NN  2048
#define DD  16
#define KK  32
#define MM  64
#define FULLM 0xffffffffu
typedef unsigned long long ull;
#define INF32 0xffffffffu
#define INF64 0xFFFFFFFFFFFFFFFFull

// scratch (allocation-free rule: device globals)
__device__ int   g_nbr  [BSZ*CC*NN*KK];
__device__ float g_theta[BSZ*CC*NN*KK];
__device__ float g_gate [BSZ*CC*NN*KK];
__device__ float g_gsum [BSZ*CC*NN];
__device__ float g_awT  [128*MM];

__device__ __forceinline__ ull warpmin64(ull p) {
    #pragma unroll
    for (int o = 16; o; o >>= 1) {
        ull q = __shfl_xor_sync(FULLM, p, o);
        if (q < p) p = q;
    }
    return p;
}

// bitonic compare-exchange (warp-wide, 2 elements/lane)
__device__ __forceinline__ float cexf(float v, int j, bool up, int lane) {
    float o = __shfl_xor_sync(FULLM, v, j);
    bool low = ((lane & j) == 0);
    float mn = fminf(v, o), mx = fmaxf(v, o);
    return (low == up) ? mn : mx;
}
__device__ __forceinline__ ull cex64(ull v, int j, bool up, int lane) {
    ull o = __shfl_xor_sync(FULLM, v, j);
    bool low = ((lane & j) == 0);
    ull mn = (v < o) ? v : o;
    ull mx = (v < o) ? o : v;
    return (low == up) ? mn : mx;
}

__device__ __forceinline__ void emit_row(
    int slice, int b, int i, unsigned nbd, int nbj,
    float Spos, const float* node_mask, const float4* spos, int lane)
{
    const float4 pi  = spos[i];
    const float mk   = node_mask[b*NN + i];
    const float dist = __uint_as_float(nbd);
    const int   nb   = nbj;

    const int nb0 = __shfl_sync(FULLM, nbj, 0);
    float4 pn0 = spos[nb0];
    float d0x = pn0.x - pi.x, d0y = pn0.y - pi.y, d0z = pn0.z - pi.z;
    float n0  = sqrtf(d0x*d0x + d0y*d0y + d0z*d0z);
    float inv0 = 1.f / fmaxf(n0, 1e-12f);
    d0x *= inv0; d0y *= inv0; d0z *= inv0;

    float cosv = 1.f;
    if (lane > 0) {
        float4 pn = spos[nb];
        float dx = pn.x - pi.x, dy = pn.y - pi.y, dz = pn.z - pi.z;
        float nrm = sqrtf(dx*dx + dy*dy + dz*dz);
        float inv = 1.f / fmaxf(nrm, 1e-12f);
        cosv = (dx*d0x + dy*d0y + dz*d0z) * inv;
    }
    const float gb   = fmaxf(dist * Spos, 0.f) * mk;
    const float gate = 1.f / (1.f + __expf(-gb));

    float G = gate;
    #pragma unroll
    for (int o = 16; o; o >>= 1) G += __shfl_xor_sync(FULLM, G, o);

    const size_t base = ((size_t)slice * NN + i) * KK;
    g_nbr  [base + lane] = nb;
    g_theta[base + lane] = cosv * mk;
    g_gate [base + lane] = gate;
    if (lane == 0) g_gsum[(size_t)slice*NN + i] = G;
}

// process one row's survivor buffer: sort 64 padded keys, ranks 1..32
__device__ __forceinline__ void select_row(
    int slice, int b, int i, const float4* spos, ull* row, int S,
    float Spos, const float* node_mask, int lane)
{
    unsigned nbd = 0; int nbj = 0;
    if (S <= 64) {
        ull V0 = row[lane], V1 = row[lane + 32];
        #pragma unroll
        for (int k = 2; k <= 32; k <<= 1) {
            #pragma unroll
            for (int j = k >> 1; j > 0; j >>= 1) {
                bool up0 = ((lane & k) == 0);
                bool up1 = (((lane + 32) & k) == 0);
                V0 = cex64(V0, j, up0, lane);
                V1 = cex64(V1, j, up1, lane);
            }
        }
        { ull lo = (V0 < V1) ? V0 : V1; ull hi = (V0 < V1) ? V1 : V0;
          V0 = lo; V1 = hi; }
        #pragma unroll
        for (int j = 16; j > 0; j >>= 1) {
            V0 = cex64(V0, j, true, lane);
            V1 = cex64(V1, j, true, lane);
        }
        ull a  = __shfl_sync(FULLM, V0, (lane + 1) & 31);
        ull bq = __shfl_sync(FULLM, V1, 0);
        ull kk = (lane == 31) ? bq : a;
        nbd = (unsigned)(kk >> 32); nbj = (int)(unsigned)kk;
    } else {
        // exact slow fallback (degenerate data only)
        const float4 pi = spos[i];
        ull last = 0;
        #pragma unroll 1
        for (int e = 0; e <= 32; e++) {
            ull best = INF64;
            for (int t = 0; t < 64; t++) {
                const int j = t*32 + lane;
                float4 pj = spos[j];
                float dot = fmaf(pi.z, pj.z, fmaf(pi.y, pj.y, pi.x * pj.x));
                float d   = fmaxf(fmaf(-2.f, dot, pj.w) + pi.w, 0.f);
                ull key = ((ull)__float_as_uint(d) << 32) | (unsigned)j;
                if ((e == 0 || key > last) && key < best) best = key;
            }
            ull wm = warpmin64(best);
            if (lane == e - 1) { nbd = (unsigned)(wm >> 32); nbj = (int)(unsigned)wm; }
            last = wm;
        }
    }
    emit_row(slice, b, i, nbd, nbj, Spos, node_mask, spos, lane);
}

// ---------------------------------------------------------------------------
// Kernel 1 v9.1: 2 rows/warp threshold select. Pass1: FMNMX top-2 d heads
// (no indices), shared pj loads. Sort heads -> T. Pass2: compact (d<=T).
// Sort survivors -> ranks 1..32. 48.5KB dyn smem, occ 3.
// ---------------------------------------------------------------------------
__global__ __launch_bounds__(512, 3) void knn_kernel(
    const float* __restrict__ pos, const float* __restrict__ node_mask,
    const float* __restrict__ rw1, const float* __restrict__ rw2,
    const float* __restrict__ aw)
{
    extern __shared__ char sm1[];
    float4* spos = (float4*)sm1;                       // 32KB
    ull*    srow = (ull*)(sm1 + NN*16);                // 32 rows x 64 = 16KB
    __shared__ int   scnt[32];
    __shared__ float sSpos;

    const int tid  = threadIdx.x;
    const int warp = tid >> 5;
    const int lane = tid & 31;
    const int slice = blockIdx.y;          // b*C + c
    const int b     = slice >> 2;
    const float* p  = pos + (size_t)slice * NN * 3;

    for (int j = tid; j < NN; j += 512) {
        float x = p[3*j], y = p[3*j+1], z = p[3*j+2];
        float q = fmaf(z, z, fmaf(y, y, x*x));
        spos[j] = make_float4(x, y, z, q);
    }

    // fold the aw transpose into one knn block (fuse runs after knn)
    if (blockIdx.x == 0 && slice == 0) {
        for (int idx = tid; idx < 128*MM; idx += 512) {
            int f = idx >> 6, m = idx & 63;
            g_awT[idx] = aw[m*128 + f];
        }
    }

    // gate MLP collapses: relu(sum_m relu(d*w1)*w2) = relu(d*Spos) for d>=0
    if (tid < 32) {
        float a1 = rw1[tid],    w1v = rw2[tid];
        float a2 = rw1[tid+32], w2v = rw2[tid+32];
        float sp = fmaf(fmaxf(a1, 0.f), w1v, fmaxf(a2, 0.f) * w2v);
        #pragma unroll
        for (int o = 16; o; o >>= 1) sp += __shfl_xor_sync(FULLM, sp, o);
        if (tid == 0) sSpos = sp;
    }
    __syncthreads();

    const int iA = blockIdx.x * 32 + warp * 2;
    const int iB = iA + 1;
    const float4 piA = spos[iA];
    const float4 piB = spos[iB];

    // pass 1: per-lane two smallest d per row (floats, FMNMX; no indices)
    float a0 = INFINITY, a1 = INFINITY;
    float b0 = INFINITY, b1 = INFINITY;
    #pragma unroll 4
    for (int t = 0; t < 64; t++) {
        float4 pj = spos[t*32 + lane];
        float dotA = fmaf(piA.z, pj.z, fmaf(piA.y, pj.y, piA.x * pj.x));
        float dA   = fmaf(-2.f, dotA, pj.w) + piA.w;
        float tA = fmaxf(a0, dA); a0 = fminf(a0, dA); a1 = fminf(a1, tA);
        float dotB = fmaf(piB.z, pj.z, fmaf(piB.y, pj.y, piB.x * pj.x));
        float dB   = fmaf(-2.f, dotB, pj.w) + piB.w;
        float tB = fmaxf(b0, dB); b0 = fminf(b0, dB); b1 = fminf(b1, tB);
    }

    // bitonic sort 64 heads per row (2 rows interleaved); T = rank 32
    float TA, TB;
    {
        float vA0 = a0, vA1 = a1, vB0 = b0, vB1 = b1;
        #pragma unroll
        for (int k = 2; k <= 32; k <<= 1) {
            #pragma unroll
            for (int j = k >> 1; j > 0; j >>= 1) {
                bool up0 = ((lane & k) == 0);
                bool up1 = (((lane + 32) & k) == 0);
                vA0 = cexf(vA0, j, up0, lane);
                vA1 = cexf(vA1, j, up1, lane);
                vB0 = cexf(vB0, j, up0, lane);
                vB1 = cexf(vB1, j, up1, lane);
            }
        }
        { float lo = fminf(vA0, vA1), hi = fmaxf(vA0, vA1); vA0 = lo; vA1 = hi; }
        { float lo = fminf(vB0, vB1), hi = fmaxf(vB0, vB1); vB0 = lo; vB1 = hi; }
        #pragma unroll
        for (int j = 16; j > 0; j >>= 1) {
            vA0 = cexf(vA0, j, true, lane);
            vA1 = cexf(vA1, j, true, lane);
            vB0 = cexf(vB0, j, true, lane);
            vB1 = cexf(vB1, j, true, lane);
        }
        TA = __shfl_sync(FULLM, vA1, 0);
        TB = __shfl_sync(FULLM, vB1, 0);
    }

    // init survivor buffers
    ull* rowA = srow + (warp*2    ) * 64;
    ull* rowB = srow + (warp*2 + 1) * 64;
    if (lane == 0) { scnt[warp*2] = 0; scnt[warp*2+1] = 0; }
    rowA[lane] = INF64; rowA[lane+32] = INF64;
    rowB[lane] = INF64; rowB[lane+32] = INF64;
    __syncwarp();

    // pass 2: compact survivors (d <= T), shared pj loads
    #pragma unroll 4
    for (int t = 0; t < 64; t++) {
        const int j = t*32 + lane;
        float4 pj = spos[j];
        float dotA = fmaf(piA.z, pj.z, fmaf(piA.y, pj.y, piA.x * pj.x));
        float dA   = fmaf(-2.f, dotA, pj.w) + piA.w;
        if (dA <= TA) {
            unsigned u = __float_as_uint(fmaxf(dA, 0.f));
            int idx = atomicAdd(&scnt[warp*2], 1);
            if (idx < 64) rowA[idx] = ((ull)u << 32) | (unsigned)j;
        }
        float dotB = fmaf(piB.z, pj.z, fmaf(piB.y, pj.y, piB.x * pj.x));
        float dB   = fmaf(-2.f, dotB, pj.w) + piB.w;
        if (dB <= TB) {
            unsigned u = __float_as_uint(fmaxf(dB, 0.f));
            int idx = atomicAdd(&scnt[warp*2+1], 1);
            if (idx < 64) rowB[idx] = ((ull)u << 32) | (unsigned)j;
        }
    }
    __syncwarp();

    const float Spos = sSpos;
    select_row(slice, b, iA, spos, rowA, scnt[warp*2],   Spos, node_mask, lane);
    select_row(slice, b, iB, spos, rowB, scnt[warp*2+1], Spos, node_mask, lane);
}

// ---------------------------------------------------------------------------
// Kernel 2 (R9 exact): 32 nodes/block (grid 256), weights from L1-global,
// 35KB smem. Block 256, tile 4m x 2n.
// ---------------------------------------------------------------------------
__global__ __launch_bounds__(256) void fuse_kernel(
    const float* __restrict__ node_fea, const float* __restrict__ node_mask,
    const float* __restrict__ sw, float* __restrict__ out)
{
    __shared__ float su [128*34];          // [f][n pitch34]
    __shared__ float sth[128*34];

    const int tid = threadIdx.x;
    const int b   = blockIdx.x >> 6;       // 64 blocks per batch
    const int n0  = (blockIdx.x & 63) * 32;

    // stage theta -> [f = k*4+c][n]
    for (int idx = tid; idx < 4096; idx += 256) {
        int c = idx >> 10, r = idx & 1023, n = r >> 5, k = r & 31;
        sth[(k*4 + c)*34 + n] =
            g_theta[(((size_t)(b*CC + c))*NN + n0 + n)*KK + k];
    }

    // phase A: thread = (c, nn, half) builds 8 nbr-f + 8 self-f of su[f][n]
    {
        const int c = tid >> 6, r = tid & 63, nn = r >> 1, half = r & 1;
        const float* nf = node_fea + (size_t)(b*CC + c) * NN * DD;
        const float mk = node_mask[b*NN + n0 + nn];
        const float G  = g_gsum[(size_t)(b*CC + c)*NN + n0 + nn];
        const size_t eb = ((size_t)(b*CC + c)*NN + n0 + nn) * KK;

        float4 a0 = {0,0,0,0}, a1 = {0,0,0,0};
        #pragma unroll 2
        for (int k4 = 0; k4 < 8; k4++) {
            float4 g4 = __ldg((const float4*)(g_gate + eb) + k4);
            int4   n4 = __ldg((const int4*)  (g_nbr  + eb) + k4);
            const float gs[4] = {g4.x, g4.y, g4.z, g4.w};
            const int   ns[4] = {n4.x, n4.y, n4.z, n4.w};
            #pragma unroll
            for (int e = 0; e < 4; e++) {
                const float4* vp =
                    (const float4*)(nf + (size_t)ns[e]*DD) + half*2;
                float4 v0 = __ldg(vp), v1 = __ldg(vp + 1);
                float g = gs[e];
                a0.x = fmaf(g, v0.x, a0.x); a0.y = fmaf(g, v0.y, a0.y);
                a0.z = fmaf(g, v0.z, a0.z); a0.w = fmaf(g, v0.w, a0.w);
                a1.x = fmaf(g, v1.x, a1.x); a1.y = fmaf(g, v1.y, a1.y);
                a1.z = fmaf(g, v1.z, a1.z); a1.w = fmaf(g, v1.w, a1.w);
            }
        }
        const int fn = c*32 + 16 + half*8;     // neighbor block (masked)
        su[(fn+0)*34+nn] = a0.x*mk;  su[(fn+1)*34+nn] = a0.y*mk;
        su[(fn+2)*34+nn] = a0.z*mk;  su[(fn+3)*34+nn] = a0.w*mk;
        su[(fn+4)*34+nn] = a1.x*mk;  su[(fn+5)*34+nn] = a1.y*mk;
        su[(fn+6)*34+nn] = a1.z*mk;  su[(fn+7)*34+nn] = a1.w*mk;

        const float Gm = G * mk;               // self block
        const float4* fp = (const float4*)(nf + (size_t)(n0+nn)*DD) + half*2;
        float4 f0 = __ldg(fp), f1 = __ldg(fp + 1);
        const int fs = c*32 + half*8;
        su[(fs+0)*34+nn] = Gm*f0.x;  su[(fs+1)*34+nn] = Gm*f0.y;
        su[(fs+2)*34+nn] = Gm*f0.z;  su[(fs+3)*34+nn] = Gm*f0.w;
        su[(fs+4)*34+nn] = Gm*f1.x;  su[(fs+5)*34+nn] = Gm*f1.y;
        su[(fs+6)*34+nn] = Gm*f1.z;  su[(fs+7)*34+nn] = Gm*f1.w;
    }
    __syncthreads();

    // phase B: thread tile 4m x 2n, weights streamed from global (L1-hot)
    {
        const int mg = (tid & 15) * 4;
        const int ng = tid >> 4;               // n = ng*2 + {0,1}
        float acc[4][2];
        #pragma unroll
        for (int a = 0; a < 4; a++) { acc[a][0] = 0.f; acc[a][1] = 0.f; }

        #pragma unroll 4
        for (int f = 0; f < 128; f++) {
            float4 w1 = __ldg((const float4*)(sw    + f*64 + mg));
            float4 w2 = __ldg((const float4*)(g_awT + f*64 + mg));
            float2 uu = *(const float2*)&su [f*34 + ng*2];
            float2 tt = *(const float2*)&sth[f*34 + ng*2];
            const float wm1[4] = {w1.x, w1.y, w1.z, w1.w};
            const float wm2[4] = {w2.x, w2.y, w2.z, w2.w};
            #pragma unroll
            for (int a = 0; a < 4; a++) {
                acc[a][0] = fmaf(wm1[a], uu.x, fmaf(wm2[a], tt.x, acc[a][0]));
                acc[a][1] = fmaf(wm1[a], uu.y, fmaf(wm2[a], tt.y, acc[a][1]));
            }
        }

        const float mk0 = node_mask[b*NN + n0 + ng*2];
        const float mk1 = node_mask[b*NN + n0 + ng*2 + 1];
        #pragma unroll
        for (int a = 0; a < 4; a++) {
            float v0 = acc[a][0], v1 = acc[a][1];
            v0 = (v0 >= 0.f) ? v0 : 0.01f*v0;
            v1 = (v1 >= 0.f) ? v1 : 0.01f*v1;
            float2 o2 = make_float2(v0*mk0, v1*mk1);
            *(float2*)&out[((size_t)b*MM + mg + a)*NN + n0 + ng*2] = o2;
        }
    }
}

// ---------------------------------------------------------------------------
extern "C" void kernel_launch(void* const* d_in, const int* in_sizes, int n_in,
                              void* d_out, int out_size)
{
    const float* pos       = (const float*)d_in[0];
    const float* node_fea  = (const float*)d_in[1];
    const float* node_mask = (const float*)d_in[2];
    const float* aw        = (const float*)d_in[3];
    const float* sw        = (const float*)d_in[4];
    const float* rw1       = (const float*)d_in[5];
    const float* rw2       = (const float*)d_in[6];
    float* out = (float*)d_out;

    const int smem1 = NN*16 + 32*64*8;     // 49152
    cudaFuncSetAttribute(knn_kernel,
        cudaFuncAttributeMaxDynamicSharedMemorySize, smem1);

    knn_kernel<<<dim3(NN/32, BSZ*CC), 512, smem1>>>(pos, node_mask, rw1, rw2, aw);
    fuse_kernel<<<BSZ*(NN/32), 256>>>(node_fea, node_mask, sw, out);
}